// round 15
// baseline (speedup 1.0000x reference)
#include <cuda_runtime.h>
#include <cuda_bf16.h>
#include <cstdint>

#define HH 512
#define WW 512
#define HWSZ (HH*WW)
#define CHSZ ((size_t)HWSZ*64)
#define TS 2048
#define NSTRIP 8

__device__ __align__(128) __nv_bfloat16 g_actA[(size_t)16*HWSZ*64];
__device__ __align__(128) __nv_bfloat16 g_actB[(size_t)8*HWSZ*64];
__device__ __align__(128) __nv_bfloat16 g_w2[9437184];
__device__ __align__(128) __nv_bfloat16 g_Vhi[(size_t)36*8*TS*64];
__device__ __align__(128) __nv_bfloat16 g_Vlo[(size_t)36*8*TS*64];
__device__ __align__(128) float g_M[(size_t)36*512*TS];
__device__ float g_tmp[HWSZ];

#define XPART 33024
#define XBUF 66048
#define WOFF 132096
#define WPART 16384
#define WBUF 32768
#define SMEM_TOTAL 197632
#define X2PART 65792
#define W2OFF 131584
#define W2PART 8192
#define W2TAP 16384
#define SMEM2_TOTAL 180736
#define GXPART 32768
#define GXBUF 65536
#define GWOFF 131072
#define GWPART 16384
#define GWBUF 32768
#define GSMEM 196608

__device__ __forceinline__ uint32_t smem_u32(const void* p) {
    uint32_t a;
    asm("{ .reg .u64 t; cvta.to.shared.u64 t, %1; cvt.u32.u64 %0, t; }" : "=r"(a) : "l"(p));
    return a;
}
__device__ __forceinline__ void cp16(uint32_t dst, const void* src, uint32_t n) {
    asm volatile("cp.async.cg.shared.global [%0], [%1], 16, %2;"
                 :: "r"(dst), "l"(src), "r"(n) : "memory");
}
__device__ __forceinline__ void ldsm4(uint32_t (&r)[4], uint32_t a) {
    asm volatile("ldmatrix.sync.aligned.m8n8.x4.shared.b16 {%0,%1,%2,%3}, [%4];"
                 : "=r"(r[0]), "=r"(r[1]), "=r"(r[2]), "=r"(r[3]) : "r"(a));
}
__device__ __forceinline__ void mma16816(float* c, const uint32_t* a, const uint32_t* b) {
    asm volatile(
        "mma.sync.aligned.m16n8k16.row.col.f32.bf16.bf16.f32 "
        "{%0,%1,%2,%3}, {%4,%5,%6,%7}, {%8,%9}, {%0,%1,%2,%3};"
        : "+f"(c[0]), "+f"(c[1]), "+f"(c[2]), "+f"(c[3])
        : "r"(a[0]), "r"(a[1]), "r"(a[2]), "r"(a[3]), "r"(b[0]), "r"(b[1]));
}
__device__ __forceinline__ void split_store(__nv_bfloat16* hi_p, __nv_bfloat16* lo_p, float v) {
    __nv_bfloat16 h = __float2bfloat16(v);
    *hi_p = h;
    *lo_p = __float2bfloat16(v - __bfloat162float(h));
}

// ---------------- direct-path weight transform (9 taps) ----------------
__global__ void wtrans_kernel(const float* __restrict__ w, int cout, int coutPad,
                              int cin, int nck) {
    int e = blockIdx.x * blockDim.x + threadIdx.x;
    if (e >= 2 * nck * 9 * coutPad * 64) return;
    int sc  = e & 63;
    int co  = (e >> 6) % coutPad;
    int blk = e / (64 * coutPad);
    int tap = blk % 9, ck2 = blk / 9;
    int part = (ck2 >= nck) ? 1 : 0;
    int ck = part ? ck2 - nck : ck2;
    int c = sc ^ ((co & 7) << 3);
    float v = 0.f;
    if (co < cout) v = w[((size_t)co * cin + ck * 64 + c) * 9 + tap];
    __nv_bfloat16 h = __float2bfloat16(v);
    g_w2[e] = part ? __float2bfloat16(v - __bfloat162float(h)) : h;
}

// ---------------- winograd F(4,3) weight transform (fast) ----------------
__global__ void wg_wtrans_kernel(const float* __restrict__ w, int cout, int coutPad,
                                 int cin, int nck) {
    int e = blockIdx.x * blockDim.x + threadIdx.x;
    if (e >= nck * coutPad * 32) return;
    int c2 = e & 31;
    int co = (e >> 5) % coutPad;
    int ck = e / (32 * coutPad);
    int s = (co & 7) << 3;
    int sc0 = 2 * c2;
    int ca = sc0 ^ s;
    float U[2][36];
#pragma unroll
    for (int ch = 0; ch < 2; ch++) {
        float g[9];
#pragma unroll
        for (int i = 0; i < 9; i++) g[i] = 0.f;
        if (co < cout) {
            const float* gw = &w[((size_t)co * cin + ck * 64 + ca + ch) * 9];
#pragma unroll
            for (int i = 0; i < 9; i++) g[i] = gw[i];
        }
        float T1[6][3];
#pragma unroll
        for (int b = 0; b < 3; b++) {
            float a0 = g[b], a1 = g[3 + b], a2 = g[6 + b];
            T1[0][b] = 0.25f * a0;
            T1[1][b] = (-1.f / 6.f) * (a0 + a1 + a2);
            T1[2][b] = (1.f / 6.f) * (-a0 + a1 - a2);
            T1[3][b] = (1.f / 24.f) * a0 + (1.f / 12.f) * a1 + (1.f / 6.f) * a2;
            T1[4][b] = (1.f / 24.f) * a0 - (1.f / 12.f) * a1 + (1.f / 6.f) * a2;
            T1[5][b] = a2;
        }
#pragma unroll
        for (int i = 0; i < 6; i++) {
            float t0 = T1[i][0], t1 = T1[i][1], t2 = T1[i][2];
            U[ch][i * 6 + 0] = 0.25f * t0;
            U[ch][i * 6 + 1] = (-1.f / 6.f) * (t0 + t1 + t2);
            U[ch][i * 6 + 2] = (1.f / 6.f) * (-t0 + t1 - t2);
            U[ch][i * 6 + 3] = (1.f / 24.f) * t0 + (1.f / 12.f) * t1 + (1.f / 6.f) * t2;
            U[ch][i * 6 + 4] = (1.f / 24.f) * t0 - (1.f / 12.f) * t1 + (1.f / 6.f) * t2;
            U[ch][i * 6 + 5] = t2;
        }
    }
#pragma unroll
    for (int t = 0; t < 36; t++) {
        __nv_bfloat16 h0 = __float2bfloat16(U[0][t]);
        __nv_bfloat16 h1 = __float2bfloat16(U[1][t]);
        __nv_bfloat16 l0 = __float2bfloat16(U[0][t] - __bfloat162float(h0));
        __nv_bfloat16 l1 = __float2bfloat16(U[1][t] - __bfloat162float(h1));
        size_t offHi = ((size_t)(ck * 36 + t) * coutPad + co) * 64 + sc0;
        size_t offLo = ((size_t)((nck + ck) * 36 + t) * coutPad + co) * 64 + sc0;
        *(__nv_bfloat162*)&g_w2[offHi] = __nv_bfloat162(h0, h1);
        *(__nv_bfloat162*)&g_w2[offLo] = __nv_bfloat162(l0, l1);
    }
}

// ---------------- winograd F(4,3) input transform (one strip) ----------------
// fp32In: activations stored as fp32 HWC chunks; else bf16 hi/lo pairs.
__global__ __launch_bounds__(256, 1) void wg_xtrans_kernel(
    const __nv_bfloat16* __restrict__ actIn, int nckIn, int tyBase, int fp32In) {
    extern __shared__ __align__(16) float xs[];  // [18][18][64]
    int tid = threadIdx.x;
    int ck = blockIdx.z;
    int tx0 = blockIdx.x * 4;
    int lty0 = blockIdx.y * 4;
    int ty0 = tyBase + lty0;
    int px0 = tx0 * 4 - 1, py0 = ty0 * 4 - 1;
    const __nv_bfloat16* hiB = actIn + (size_t)ck * CHSZ;
    const __nv_bfloat16* loB = actIn + (size_t)(nckIn + ck) * CHSZ;
    const float* fB = (const float*)actIn + (size_t)ck * CHSZ;

    for (int i = tid; i < 18 * 18 * 32; i += 256) {
        int c2 = i & 31, rem = i >> 5;
        int cc = rem % 18, r = rem / 18;
        int gy = py0 + r, gx = px0 + cc;
        float2 v = make_float2(0.f, 0.f);
        if ((unsigned)gy < HH && (unsigned)gx < WW) {
            size_t idx = ((size_t)(gy * WW + gx)) * 64 + c2 * 2;
            if (fp32In) {
                v = *(const float2*)&fB[idx];
            } else {
                float2 h = __bfloat1622float2(*(const __nv_bfloat162*)&hiB[idx]);
                float2 l = __bfloat1622float2(*(const __nv_bfloat162*)&loB[idx]);
                v = make_float2(h.x + l.x, h.y + l.y);
            }
        }
        *(float2*)&xs[(r * 18 + cc) * 64 + c2 * 2] = v;
    }
    __syncthreads();

    for (int i8 = tid; i8 < 512; i8 += 256) {
        int c2 = i8 & 31, tl = i8 >> 5;
        int tiy = tl >> 2, tix = tl & 3;
        int c = c2 * 2;
        float Va[36], Vb[36];
#pragma unroll
        for (int ch = 0; ch < 2; ch++) {
            float t[6][6];
#pragma unroll
            for (int j = 0; j < 6; j++) {
                float d0 = xs[((4 * tiy + 0) * 18 + 4 * tix + j) * 64 + c + ch];
                float d1 = xs[((4 * tiy + 1) * 18 + 4 * tix + j) * 64 + c + ch];
                float d2 = xs[((4 * tiy + 2) * 18 + 4 * tix + j) * 64 + c + ch];
                float d3 = xs[((4 * tiy + 3) * 18 + 4 * tix + j) * 64 + c + ch];
                float d4 = xs[((4 * tiy + 4) * 18 + 4 * tix + j) * 64 + c + ch];
                float d5 = xs[((4 * tiy + 5) * 18 + 4 * tix + j) * 64 + c + ch];
                t[0][j] = 4.f * d0 - 5.f * d2 + d4;
                t[1][j] = -4.f * d1 - 4.f * d2 + d3 + d4;
                t[2][j] = 4.f * d1 - 4.f * d2 - d3 + d4;
                t[3][j] = -2.f * d1 - d2 + 2.f * d3 + d4;
                t[4][j] = 2.f * d1 - d2 - 2.f * d3 + d4;
                t[5][j] = 4.f * d1 - 5.f * d3 + d5;
            }
            float* V = ch ? Vb : Va;
#pragma unroll
            for (int i2 = 0; i2 < 6; i2++) {
                V[i2 * 6 + 0] = 4.f * t[i2][0] - 5.f * t[i2][2] + t[i2][4];
                V[i2 * 6 + 1] = -4.f * t[i2][1] - 4.f * t[i2][2] + t[i2][3] + t[i2][4];
                V[i2 * 6 + 2] = 4.f * t[i2][1] - 4.f * t[i2][2] - t[i2][3] + t[i2][4];
                V[i2 * 6 + 3] = -2.f * t[i2][1] - t[i2][2] + 2.f * t[i2][3] + t[i2][4];
                V[i2 * 6 + 4] = 2.f * t[i2][1] - t[i2][2] - 2.f * t[i2][3] + t[i2][4];
                V[i2 * 6 + 5] = 4.f * t[i2][1] - 5.f * t[i2][3] + t[i2][5];
            }
        }
        size_t ltile = (size_t)(lty0 + tiy) * 128 + tx0 + tix;
#pragma unroll
        for (int t2 = 0; t2 < 36; t2++) {
            __nv_bfloat16 ha = __float2bfloat16(Va[t2]);
            __nv_bfloat16 hb = __float2bfloat16(Vb[t2]);
            __nv_bfloat16 la = __float2bfloat16(Va[t2] - __bfloat162float(ha));
            __nv_bfloat16 lb = __float2bfloat16(Vb[t2] - __bfloat162float(hb));
            size_t off = ((size_t)(t2 * nckIn + ck) * TS + ltile) * 64 + c;
            *(__nv_bfloat162*)&g_Vhi[off] = __nv_bfloat162(ha, hb);
            *(__nv_bfloat162*)&g_Vlo[off] = __nv_bfloat162(la, lb);
        }
    }
}

// ---------------- winograd GEMM (3-term split bf16, one strip) ----------------
__global__ __launch_bounds__(256, 1) void wg_gemm_kernel(int nck, int coutTot) {
    extern __shared__ __align__(128) char sm[];
    const int tid = threadIdx.x;
    const int lane = tid & 31, wid = tid >> 5;
    const int cg = wid >> 2, pg = wid & 3;
    const int cout0 = blockIdx.x * 128;
    const int coutPad = gridDim.x * 128;
    const int tile0 = blockIdx.y * 256;
    const int comp = blockIdx.z;
    const uint32_t sb = smem_u32(sm);

    float acc[4][8][4];
#pragma unroll
    for (int a = 0; a < 4; a++)
#pragma unroll
        for (int b2 = 0; b2 < 8; b2++)
#pragma unroll
            for (int c = 0; c < 4; c++) acc[a][b2][c] = 0.f;

    const int l7 = lane & 7;
    const int arow_base = cg * 64 + ((lane >> 3) & 1) * 8 + l7;
    const int akg_add = lane >> 4;
    const int bpx_base = pg * 64 + ((lane >> 4) & 1) * 8 + l7;
    const int bkg_add = (lane >> 3) & 1;

    auto stage_it = [&](int ck) {
        uint32_t wdst = sb + GWOFF + (ck & 1) * GWBUF;
        for (int i = tid; i < 2048; i += 256) {
            int part = i >> 10, r3 = i & 1023;
            const char* src = (const char*)g_w2 +
                ((size_t)((part * nck + ck) * 36 + comp) * coutPad + cout0) * 128 + r3 * 16;
            cp16(wdst + part * GWPART + r3 * 16, src, 16u);
        }
        uint32_t xdst = sb + (ck & 1) * GXBUF;
        for (int i = tid; i < 4096; i += 256) {
            int part = i >> 11, rem = i & 2047;
            int xi = rem >> 3, gs = rem & 7;
            const char* src = (const char*)(part ? g_Vlo : g_Vhi) +
                ((size_t)(comp * nck + ck) * TS + tile0 + xi) * 128 + gs * 16;
            cp16(xdst + part * GXPART + xi * 128 + ((gs ^ (xi & 7)) << 4), src, 16u);
        }
        asm volatile("cp.async.commit_group;" ::: "memory");
    };

    stage_it(0);
    for (int it = 0; it < nck; it++) {
        asm volatile("cp.async.wait_group 0;" ::: "memory");
        __syncthreads();
        if (it + 1 < nck) stage_it(it + 1);

        uint32_t wcur = sb + GWOFF + (it & 1) * GWBUF;
        uint32_t xcur = sb + (it & 1) * GXBUF;
#pragma unroll
        for (int kk = 0; kk < 4; kk++) {
            uint32_t Ah[4][4], Al[4][4], Bf[4][4];
            uint32_t akg = ((uint32_t)(kk * 2 + akg_add) ^ (uint32_t)l7) << 4;
#pragma unroll
            for (int mf = 0; mf < 4; mf++)
                ldsm4(Ah[mf], wcur + (arow_base + mf * 16) * 128 + akg);
#pragma unroll
            for (int q = 0; q < 4; q++) {
                int xi = bpx_base + q * 16;
                ldsm4(Bf[q], xcur + xi * 128 + (((uint32_t)(kk * 2 + bkg_add) ^ (uint32_t)(xi & 7)) << 4));
            }
#pragma unroll
            for (int mf = 0; mf < 4; mf++)
#pragma unroll
                for (int q = 0; q < 4; q++) {
                    mma16816(acc[mf][2 * q], Ah[mf], &Bf[q][0]);
                    mma16816(acc[mf][2 * q + 1], Ah[mf], &Bf[q][2]);
                }
#pragma unroll
            for (int mf = 0; mf < 4; mf++)
                ldsm4(Al[mf], wcur + GWPART + (arow_base + mf * 16) * 128 + akg);
#pragma unroll
            for (int mf = 0; mf < 4; mf++)
#pragma unroll
                for (int q = 0; q < 4; q++) {
                    mma16816(acc[mf][2 * q], Al[mf], &Bf[q][0]);
                    mma16816(acc[mf][2 * q + 1], Al[mf], &Bf[q][2]);
                }
#pragma unroll
            for (int q = 0; q < 4; q++) {
                int xi = bpx_base + q * 16;
                ldsm4(Bf[q], xcur + GXPART + xi * 128 + (((uint32_t)(kk * 2 + bkg_add) ^ (uint32_t)(xi & 7)) << 4));
            }
#pragma unroll
            for (int mf = 0; mf < 4; mf++)
#pragma unroll
                for (int q = 0; q < 4; q++) {
                    mma16816(acc[mf][2 * q], Ah[mf], &Bf[q][0]);
                    mma16816(acc[mf][2 * q + 1], Ah[mf], &Bf[q][2]);
                }
        }
    }

    float* Mp = g_M + (size_t)comp * coutTot * TS;
#pragma unroll
    for (int mf = 0; mf < 4; mf++) {
        int co = cout0 + cg * 64 + mf * 16 + (lane >> 2);
#pragma unroll
        for (int nf = 0; nf < 8; nf++) {
            int tile = tile0 + pg * 64 + nf * 8 + ((lane & 3) << 1);
            *(float2*)&Mp[(size_t)co * TS + tile] = make_float2(acc[mf][nf][0], acc[mf][nf][1]);
            *(float2*)&Mp[(size_t)(co + 8) * TS + tile] = make_float2(acc[mf][nf][2], acc[mf][nf][3]);
        }
    }
}

// ---------------- winograd F(4,3) output transform (one strip) ----------------
// fp32Out: write fp32 HWC chunks (consumed by fp32In xtrans); else bf16 hi/lo.
__global__ __launch_bounds__(256, 1) void wg_ytrans_kernel(
    __nv_bfloat16* __restrict__ actOut, const float* __restrict__ bias,
    const float* __restrict__ prelu, int coutTot, int nckOut, int tyBase, int fp32Out) {
    extern __shared__ __align__(16) char ysm[];
    __nv_bfloat16* ysHi = (__nv_bfloat16*)ysm;
    __nv_bfloat16* ysLo = (__nv_bfloat16*)(ysm + 65536);
    float* ysF = (float*)ysm;   // fp32 mode: [4][128][64] floats = 128KB
    int tid = threadIdx.x;
    int tx0t = blockIdx.x * 32;
    int lty = blockIdx.y;
    int co0 = blockIdx.z * 64;
    float alpha = prelu[0];

    for (int i = tid; i < 2048; i += 256) {
        int tl = i & 31, cl = i >> 5;
        int co = co0 + cl;
        size_t ltile = (size_t)lty * 128 + tx0t + tl;
        float q[4][6];
#pragma unroll
        for (int l = 0; l < 6; l++) {
            float m0 = g_M[((size_t)(0 * 6 + l) * coutTot + co) * TS + ltile];
            float m1 = g_M[((size_t)(1 * 6 + l) * coutTot + co) * TS + ltile];
            float m2 = g_M[((size_t)(2 * 6 + l) * coutTot + co) * TS + ltile];
            float m3 = g_M[((size_t)(3 * 6 + l) * coutTot + co) * TS + ltile];
            float m4 = g_M[((size_t)(4 * 6 + l) * coutTot + co) * TS + ltile];
            float m5 = g_M[((size_t)(5 * 6 + l) * coutTot + co) * TS + ltile];
            q[0][l] = m0 + m1 + m2 + m3 + m4;
            q[1][l] = m1 - m2 + 2.f * (m3 - m4);
            q[2][l] = m1 + m2 + 4.f * (m3 + m4);
            q[3][l] = m1 - m2 + 8.f * (m3 - m4) + m5;
        }
        float bv = bias[co];
#pragma unroll
        for (int r = 0; r < 4; r++) {
            float y0 = q[r][0] + q[r][1] + q[r][2] + q[r][3] + q[r][4] + bv;
            float y1 = q[r][1] - q[r][2] + 2.f * (q[r][3] - q[r][4]) + bv;
            float y2 = q[r][1] + q[r][2] + 4.f * (q[r][3] + q[r][4]) + bv;
            float y3 = q[r][1] - q[r][2] + 8.f * (q[r][3] - q[r][4]) + q[r][5] + bv;
            float ys[4] = {y0, y1, y2, y3};
#pragma unroll
            for (int s = 0; s < 4; s++) {
                float v = ys[s];
                v = v >= 0.f ? v : alpha * v;
                int px = tl * 4 + s;
                int pc = cl ^ ((px & 7) << 3);
                if (fp32Out) {
                    ysF[(r * 128 + px) * 64 + pc] = v;
                } else {
                    __nv_bfloat16 h = __float2bfloat16(v);
                    ysHi[(r * 128 + px) * 64 + pc] = h;
                    ysLo[(r * 128 + px) * 64 + pc] = __float2bfloat16(v - __bfloat162float(h));
                }
            }
        }
    }
    __syncthreads();

    int chunk = co0 >> 6;
    if (fp32Out) {
        float* fo = (float*)actOut;
        for (int i = tid; i < 8192; i += 256) {
            int r = i >> 11, rem = i & 2047;
            int px = rem >> 4, qg = rem & 15;          // 16 channel-quads per pixel
            int q2 = qg ^ ((px & 7) << 1);             // inverse of pc swizzle at quad level
            int gy = (tyBase + lty) * 4 + r, gx = tx0t * 4 + px;
            size_t off = (size_t)chunk * CHSZ + ((size_t)(gy * WW + gx)) * 64 + qg * 4;
            *(uint4*)&fo[off] = *(uint4*)&ysF[(r * 128 + px) * 64 + q2 * 4];
        }
    } else {
        for (int i = tid; i < 4096; i += 256) {
            int r = i >> 10, rem = i & 1023;
            int px = rem >> 3, g = rem & 7;
            int pg2 = g ^ (px & 7);
            int gy = (tyBase + lty) * 4 + r, gx = tx0t * 4 + px;
            size_t off = (size_t)chunk * CHSZ + ((size_t)(gy * WW + gx)) * 64 + g * 8;
            *(uint4*)&actOut[off] = *(uint4*)&ysHi[(r * 128 + px) * 64 + pg2 * 8];
            *(uint4*)&actOut[(size_t)nckOut * CHSZ + off] = *(uint4*)&ysLo[(r * 128 + px) * 64 + pg2 * 8];
        }
    }
}

// ---------------- layer 0 ----------------
__global__ void layer0_kernel(const float* __restrict__ A, const float* __restrict__ w,
                              const float* __restrict__ b, const float* __restrict__ p) {
    int idx = blockIdx.x * blockDim.x + threadIdx.x;
    if (idx >= HWSZ) return;
    float a = A[idx], alpha = p[0];
    size_t base = (size_t)idx * 64;
#pragma unroll
    for (int c = 0; c < 64; c++) {
        float v = fmaf(w[c], a, b[c]);
        v = v >= 0.f ? v : alpha * v;
        split_store(&g_actA[base + c], &g_actA[CHSZ + base + c], v);
    }
}

// ---------------- direct conv (L1): 128 couts x 256 px ----------------
// fp32Out: epilogue writes fp32 HWC chunks (for winograd consumer).
__global__ __launch_bounds__(256, 1) void conv_mma_kernel(
    const __nv_bfloat16* __restrict__ actIn, __nv_bfloat16* __restrict__ actOut,
    const float* __restrict__ bias, const float* __restrict__ prelu,
    int nck, int nckOut, int coutReal, int fp32Out) {
    extern __shared__ __align__(128) char sm[];
    const int tid = threadIdx.x;
    const int lane = tid & 31, wid = tid >> 5;
    const int cg = wid >> 2, pg = wid & 3;
    const int cout0 = blockIdx.x * 128;
    const int coutPad = gridDim.x * 128;
    const int x0 = blockIdx.y * 256;
    const int y0 = blockIdx.z;
    const uint32_t sb = smem_u32(sm);

    float acc[4][8][4];
#pragma unroll
    for (int a = 0; a < 4; a++)
#pragma unroll
        for (int b2 = 0; b2 < 8; b2++)
#pragma unroll
            for (int c = 0; c < 4; c++) acc[a][b2][c] = 0.f;

    const int l7 = lane & 7;
    const int arow_base = cg * 64 + ((lane >> 3) & 1) * 8 + l7;
    const int akg_add = lane >> 4;
    const int bpx_base = pg * 64 + ((lane >> 4) & 1) * 8 + l7;
    const int bkg_add = (lane >> 3) & 1;
    const int niter = nck * 9;

    auto stage_it = [&](int jt) {
        int ck = jt / 9, r = jt - ck * 9, dy = r / 3, dx = r - dy * 3;
        uint32_t wdst = sb + WOFF + (jt & 1) * WBUF;
        for (int i = tid; i < 2048; i += 256) {
            int part = i >> 10;
            int r3 = i & 1023;
            const char* src = (const char*)g_w2 +
                ((((size_t)(part * nck + ck) * 9 + dy * 3 + dx)) * coutPad + cout0) * 128 +
                r3 * 16;
            cp16(wdst + part * WPART + r3 * 16, src, 16u);
        }
        if (dx == 0) {
            int y = y0 + dy - 1;
            bool yok = (unsigned)y < HH;
            uint32_t xdst = sb + ((jt / 3) & 1) * XBUF;
            for (int i = tid; i < 4128; i += 256) {
                int part = i / 2064;
                int rem = i - part * 2064;
                int xi = rem >> 3, gs = rem & 7;
                int gx = x0 - 1 + xi;
                bool ok = yok && (unsigned)gx < WW;
                const char* src = (const char*)(actIn + (size_t)(part * nck + ck) * CHSZ) +
                                  (size_t)(ok ? (y * WW + gx) : 0) * 128 + gs * 16;
                cp16(xdst + part * XPART + xi * 128 + ((gs ^ (xi & 7)) << 4), src, ok ? 16u : 0u);
            }
        }
        asm volatile("cp.async.commit_group;" ::: "memory");
    };

    stage_it(0);
    for (int it = 0; it < niter; it++) {
        asm volatile("cp.async.wait_group 0;" ::: "memory");
        __syncthreads();
        if (it + 1 < niter) stage_it(it + 1);

        int dx = it % 3;
        uint32_t wcur = sb + WOFF + (it & 1) * WBUF;
        uint32_t xcur = sb + ((it / 3) & 1) * XBUF;
#pragma unroll
        for (int kk = 0; kk < 4; kk++) {
            uint32_t Ah[4][4], Al[4][4], Bf[4][4];
            uint32_t akg = ((uint32_t)(kk * 2 + akg_add) ^ (uint32_t)l7) << 4;
#pragma unroll
            for (int mf = 0; mf < 4; mf++)
                ldsm4(Ah[mf], wcur + (arow_base + mf * 16) * 128 + akg);
#pragma unroll
            for (int q = 0; q < 4; q++) {
                int xi = bpx_base + q * 16 + dx;
                ldsm4(Bf[q], xcur + xi * 128 + (((uint32_t)(kk * 2 + bkg_add) ^ (uint32_t)(xi & 7)) << 4));
            }
#pragma unroll
            for (int mf = 0; mf < 4; mf++)
#pragma unroll
                for (int q = 0; q < 4; q++) {
                    mma16816(acc[mf][2 * q], Ah[mf], &Bf[q][0]);
                    mma16816(acc[mf][2 * q + 1], Ah[mf], &Bf[q][2]);
                }
#pragma unroll
            for (int mf = 0; mf < 4; mf++)
                ldsm4(Al[mf], wcur + WPART + (arow_base + mf * 16) * 128 + akg);
#pragma unroll
            for (int mf = 0; mf < 4; mf++)
#pragma unroll
                for (int q = 0; q < 4; q++) {
                    mma16816(acc[mf][2 * q], Al[mf], &Bf[q][0]);
                    mma16816(acc[mf][2 * q + 1], Al[mf], &Bf[q][2]);
                }
#pragma unroll
            for (int q = 0; q < 4; q++) {
                int xi = bpx_base + q * 16 + dx;
                ldsm4(Bf[q], xcur + XPART + xi * 128 + (((uint32_t)(kk * 2 + bkg_add) ^ (uint32_t)(xi & 7)) << 4));
            }
#pragma unroll
            for (int mf = 0; mf < 4; mf++)
#pragma unroll
                for (int q = 0; q < 4; q++) {
                    mma16816(acc[mf][2 * q], Ah[mf], &Bf[q][0]);
                    mma16816(acc[mf][2 * q + 1], Ah[mf], &Bf[q][2]);
                }
        }
    }
    __syncthreads();

    float* esm = (float*)sm;
    float alpha = prelu[0];
#pragma unroll
    for (int mf = 0; mf < 4; mf++) {
        int cl = cg * 64 + mf * 16 + (lane >> 2);
        float bl = (cout0 + cl < coutReal) ? bias[cout0 + cl] : 0.f;
        float bh = (cout0 + cl + 8 < coutReal) ? bias[cout0 + cl + 8] : 0.f;
#pragma unroll
        for (int nf = 0; nf < 8; nf++) {
            int p = pg * 64 + nf * 8 + ((lane & 3) << 1);
#pragma unroll
            for (int e = 0; e < 4; e++) {
                int c = cl + ((e & 2) ? 8 : 0);
                float v = acc[mf][nf][e] + ((e & 2) ? bh : bl);
                v = v >= 0.f ? v : alpha * v;
                esm[(p + (e & 1)) * 128 + c] = v;
            }
        }
    }
    __syncthreads();

    size_t rowbase = (size_t)y0 * WW + x0;
#pragma unroll
    for (int g = 0; g < 16; g++) {
        int idx = g * 256 + tid;
        int px = idx >> 4;
        int rem = idx & 15;
        int chunk = rem >> 3, grp = rem & 7;
        int cb = chunk * 64 + grp * 8;
        if (cout0 + cb >= coutReal) continue;
        const float* s = &esm[px * 128 + cb];
        size_t off = (size_t)((cout0 + cb) >> 6) * CHSZ + (rowbase + px) * 64 + (cb & 63);
        if (fp32Out) {
            float* fo = (float*)actOut;
            *(uint4*)&fo[off] = *(const uint4*)&s[0];
            *(uint4*)&fo[off + 4] = *(const uint4*)&s[4];
        } else {
            __nv_bfloat16 hi[8], lo[8];
#pragma unroll
            for (int j = 0; j < 8; j++) {
                float v = s[j];
                __nv_bfloat16 h = __float2bfloat16(v);
                hi[j] = h;
                lo[j] = __float2bfloat16(v - __bfloat162float(h));
            }
            *(uint4*)&actOut[off] = *(uint4*)hi;
            *(uint4*)&actOut[(size_t)nckOut * CHSZ + off] = *(uint4*)lo;
        }
    }
}

// ---------------- direct conv (L4): 64 couts x 512 px ----------------
__global__ __launch_bounds__(256, 1) void conv_mma64_kernel(
    const __nv_bfloat16* __restrict__ actIn, __nv_bfloat16* __restrict__ actOut,
    const float* __restrict__ bias, const float* __restrict__ prelu,
    int nck, int nckOut, int coutReal) {
    extern __shared__ __align__(128) char sm[];
    const int tid = threadIdx.x;
    const int lane = tid & 31, wid = tid >> 5;
    const int pg = wid;
    const int y0 = blockIdx.z;
    const uint32_t sb = smem_u32(sm);

    float acc[4][8][4];
#pragma unroll
    for (int a = 0; a < 4; a++)
#pragma unroll
        for (int b2 = 0; b2 < 8; b2++)
#pragma unroll
            for (int c = 0; c < 4; c++) acc[a][b2][c] = 0.f;

    const int l7 = lane & 7;
    const int arow_base = ((lane >> 3) & 1) * 8 + l7;
    const int akg_add = lane >> 4;
    const int bpx_base = pg * 64 + ((lane >> 4) & 1) * 8 + l7;
    const int bkg_add = (lane >> 3) & 1;

    for (int it2 = 0; it2 < nck * 3; it2++) {
        int ck = it2 / 3, dy = it2 - ck * 3;
        if (it2) __syncthreads();
        int y = y0 + dy - 1;
        bool yok = (unsigned)y < HH;
        for (int i = tid; i < 8224; i += 256) {
            int part = i / 4112;
            int rem = i - part * 4112;
            int xi = rem >> 3, gs = rem & 7;
            int gx = xi - 1;
            bool ok = yok && (unsigned)gx < WW;
            const char* src = (const char*)(actIn + (size_t)(part * nck + ck) * CHSZ) +
                              (size_t)(ok ? (y * WW + gx) : 0) * 128 + gs * 16;
            cp16(sb + part * X2PART + xi * 128 + ((gs ^ (xi & 7)) << 4), src, ok ? 16u : 0u);
        }
        for (int i = tid; i < 3072; i += 256) {
            int dx = i / 1024;
            int rem = i & 1023;
            int part = rem >> 9;
            int r3 = rem & 511;
            const char* src = (const char*)g_w2 +
                ((((size_t)(part * nck + ck) * 9 + dy * 3 + dx)) * 64) * 128 + r3 * 16;
            cp16(sb + W2OFF + dx * W2TAP + part * W2PART + r3 * 16, src, 16u);
        }
        asm volatile("cp.async.wait_all;" ::: "memory");
        __syncthreads();

#pragma unroll
        for (int dx = 0; dx < 3; dx++) {
            uint32_t wcur = sb + W2OFF + dx * W2TAP;
#pragma unroll
            for (int kk = 0; kk < 4; kk++) {
                uint32_t Ah[4][4], Al[4][4], Bf[4][4];
                uint32_t akg = ((uint32_t)(kk * 2 + akg_add) ^ (uint32_t)l7) << 4;
#pragma unroll
                for (int mf = 0; mf < 4; mf++)
                    ldsm4(Ah[mf], wcur + (arow_base + mf * 16) * 128 + akg);
#pragma unroll
                for (int q = 0; q < 4; q++) {
                    int xi = bpx_base + q * 16 + dx;
                    ldsm4(Bf[q], sb + xi * 128 + (((uint32_t)(kk * 2 + bkg_add) ^ (uint32_t)(xi & 7)) << 4));
                }
#pragma unroll
                for (int mf = 0; mf < 4; mf++)
#pragma unroll
                    for (int q = 0; q < 4; q++) {
                        mma16816(acc[mf][2 * q], Ah[mf], &Bf[q][0]);
                        mma16816(acc[mf][2 * q + 1], Ah[mf], &Bf[q][2]);
                    }
#pragma unroll
                for (int mf = 0; mf < 4; mf++)
                    ldsm4(Al[mf], wcur + W2PART + (arow_base + mf * 16) * 128 + akg);
#pragma unroll
                for (int mf = 0; mf < 4; mf++)
#pragma unroll
                    for (int q = 0; q < 4; q++) {
                        mma16816(acc[mf][2 * q], Al[mf], &Bf[q][0]);
                        mma16816(acc[mf][2 * q + 1], Al[mf], &Bf[q][2]);
                    }
#pragma unroll
                for (int q = 0; q < 4; q++) {
                    int xi = bpx_base + q * 16 + dx;
                    ldsm4(Bf[q], sb + X2PART + xi * 128 + (((uint32_t)(kk * 2 + bkg_add) ^ (uint32_t)(xi & 7)) << 4));
                }
#pragma unroll
                for (int mf = 0; mf < 4; mf++)
#pragma unroll
                    for (int q = 0; q < 4; q++) {
                        mma16816(acc[mf][2 * q], Ah[mf], &Bf[q][0]);
                        mma16816(acc[mf][2 * q + 1], Ah[mf], &Bf[q][2]);
                    }
            }
        }
    }
    __syncthreads();

    float* esm = (float*)sm;
    float alpha = prelu[0];
#pragma unroll
    for (int mf = 0; mf < 4; mf++) {
        int cl = mf * 16 + (lane >> 2);
        float bl = bias[cl];
        float bh = bias[cl + 8];
#pragma unroll
        for (int nf = 0; nf < 8; nf++) {
            int p = pg * 64 + nf * 8 + ((lane & 3) << 1);
#pragma unroll
            for (int e = 0; e < 4; e++) {
                int c = cl + ((e & 2) ? 8 : 0);
                float v = acc[mf][nf][e] + ((e & 2) ? bh : bl);
                v = v >= 0.f ? v : alpha * v;
                esm[(p + (e & 1)) * 64 + c] = v;
            }
        }
    }
    __syncthreads();

    size_t rowbase = (size_t)y0 * WW;
#pragma unroll
    for (int g = 0; g < 16; g++) {
        int idx = g * 256 + tid;
        int px = idx >> 3;
        int cb = (idx & 7) * 8;
        const float* s = &esm[px * 64 + cb];
        __nv_bfloat16 hi[8], lo[8];
#pragma unroll
        for (int j = 0; j < 8; j++) {
            float v = s[j];
            __nv_bfloat16 h = __float2bfloat16(v);
            hi[j] = h;
            lo[j] = __float2bfloat16(v - __bfloat162float(h));
        }
        size_t off = (rowbase + px) * 64 + cb;
        *(uint4*)&actOut[off] = *(uint4*)hi;
        *(uint4*)&actOut[(size_t)nckOut * CHSZ + off] = *(uint4*)lo;
    }
}

// ---------------- L5 + symmetrize ----------------
__global__ void conv_last_kernel(const __nv_bfloat16* __restrict__ act,
                                 const float* __restrict__ w, const float* __restrict__ b,
                                 const float* __restrict__ p, float* __restrict__ out) {
    int x = blockIdx.x * 32 + (threadIdx.x & 31);
    int y = blockIdx.y * 8 + (threadIdx.x >> 5);
    float acc = 0.f;
#pragma unroll
    for (int dy = 0; dy < 3; dy++) {
        int gy = y + dy - 1;
        if ((unsigned)gy >= HH) continue;
#pragma unroll
        for (int dx = 0; dx < 3; dx++) {
            int gx = x + dx - 1;
            if ((unsigned)gx >= WW) continue;
            size_t base = (size_t)(gy * WW + gx) * 64;
            const __nv_bfloat162* hi2 = (const __nv_bfloat162*)&act[base];
            const __nv_bfloat162* lo2 = (const __nv_bfloat162*)&act[CHSZ + base];
#pragma unroll
            for (int c2 = 0; c2 < 32; c2++) {
                float2 h = __bfloat1622float2(hi2[c2]);
                float2 l = __bfloat1622float2(lo2[c2]);
                acc = fmaf(h.x + l.x, w[(c2 * 2) * 9 + dy * 3 + dx], acc);
                acc = fmaf(h.y + l.y, w[(c2 * 2 + 1) * 9 + dy * 3 + dx], acc);
            }
        }
    }
    float v = acc + b[0];
    v = v >= 0.f ? v : p[0] * v;
    out[y * WW + x] = v;
}

__global__ void sym_kernel(const float* __restrict__ t, float* __restrict__ out) {
    int x = blockIdx.x * 32 + (threadIdx.x & 31);
    int y = blockIdx.y * 8 + (threadIdx.x >> 5);
    out[y * WW + x] = 0.5f * (t[y * WW + x] + t[x * WW + y]);
}

// ---------------------------------------------------------------------------
extern "C" void kernel_launch(void* const* d_in, const int* in_sizes, int n_in,
                              void* d_out, int out_size) {
    const float* A = (const float*)d_in[0];
    const float* wp[6]; const float* bp[6]; const float* pp[6];
    for (int i = 0; i < 6; i++) {
        wp[i] = (const float*)d_in[1 + 3 * i];
        bp[i] = (const float*)d_in[2 + 3 * i];
        pp[i] = (const float*)d_in[3 + 3 * i];
    }
    __nv_bfloat16 *actA, *actB; float* tmp;
    cudaGetSymbolAddress((void**)&actA, g_actA);
    cudaGetSymbolAddress((void**)&actB, g_actB);
    cudaGetSymbolAddress((void**)&tmp, g_tmp);

    cudaFuncSetAttribute(conv_mma_kernel, cudaFuncAttributeMaxDynamicSharedMemorySize, SMEM_TOTAL);
    cudaFuncSetAttribute(conv_mma64_kernel, cudaFuncAttributeMaxDynamicSharedMemorySize, SMEM2_TOTAL);
    cudaFuncSetAttribute(wg_gemm_kernel, cudaFuncAttributeMaxDynamicSharedMemorySize, GSMEM);
    cudaFuncSetAttribute(wg_xtrans_kernel, cudaFuncAttributeMaxDynamicSharedMemorySize, 82944);
    cudaFuncSetAttribute(wg_ytrans_kernel, cudaFuncAttributeMaxDynamicSharedMemorySize, 131072);

    layer0_kernel<<<HWSZ / 256, 256>>>(A, wp[0], bp[0], pp[0]);

    // L1 direct: 64 -> 256, fp32 output (consumed by L2 winograd xtrans)
    wtrans_kernel<<<(2 * 1 * 9 * 256 * 64 + 255) / 256, 256>>>(wp[1], 256, 256, 64, 1);
    conv_mma_kernel<<<dim3(2, WW / 256, HH), 256, SMEM_TOTAL>>>(actA, actB, bp[1], pp[1], 1, 4, 256, 1);

    // L2 winograd F(4,3): 256 -> 512, fp32 in, fp32 out (to L3 xtrans)
    wg_wtrans_kernel<<<(4 * 512 * 32 + 255) / 256, 256>>>(wp[2], 512, 512, 256, 4);
    for (int s = 0; s < NSTRIP; s++) {
        int tyBase = s * 16;
        wg_xtrans_kernel<<<dim3(32, 4, 4), 256, 82944>>>(actB, 4, tyBase, 1);
        wg_gemm_kernel<<<dim3(4, TS / 256, 36), 256, GSMEM>>>(4, 512);
        wg_ytrans_kernel<<<dim3(4, 16, 8), 256, 131072>>>(actA, bp[2], pp[2], 512, 8, tyBase, 1);
    }

    // L3 winograd F(4,3): 512 -> 256, fp32 in, bf16 hi/lo out (to L4 direct)
    wg_wtrans_kernel<<<(8 * 256 * 32 + 255) / 256, 256>>>(wp[3], 256, 256, 512, 8);
    for (int s = 0; s < NSTRIP; s++) {
        int tyBase = s * 16;
        wg_xtrans_kernel<<<dim3(32, 4, 8), 256, 82944>>>(actA, 8, tyBase, 1);
        wg_gemm_kernel<<<dim3(2, TS / 256, 36), 256, GSMEM>>>(8, 256);
        wg_ytrans_kernel<<<dim3(4, 16, 4), 256, 131072>>>(actB, bp[3], pp[3], 256, 4, tyBase, 0);
    }

    // L4 direct: 256 -> 64 (bf16 hi/lo in and out)
    wtrans_kernel<<<(2 * 4 * 9 * 64 * 64 + 255) / 256, 256>>>(wp[4], 64, 64, 256, 4);
    conv_mma64_kernel<<<dim3(1, 1, HH), 256, SMEM2_TOTAL>>>(actB, actA, bp[4], pp[4], 4, 1, 64);

    conv_last_kernel<<<dim3(WW / 32, HH / 8), 256>>>(actA, wp[5], bp[5], pp[5], tmp);
    sym_kernel<<<dim3(WW / 32, HH / 8), 256>>>(tmp, (float*)d_out);
}

// round 16
// speedup vs baseline: 1.5686x; 1.5686x over previous
#include <cuda_runtime.h>
#include <cuda_bf16.h>
#include <cstdint>

#define HH 512
#define WW 512
#define HWSZ (HH*WW)
#define CHSZ ((size_t)HWSZ*64)
#define TS 2048
#define NSTRIP 8

__device__ __align__(128) __nv_bfloat16 g_actA[(size_t)16*HWSZ*64];
__device__ __align__(128) __nv_bfloat16 g_actB[(size_t)8*HWSZ*64];
__device__ __align__(128) __nv_bfloat16 g_w2[9437184];
__device__ __align__(128) __nv_bfloat16 g_Vhi[(size_t)36*8*TS*64];
__device__ __align__(128) __nv_bfloat16 g_Vlo[(size_t)36*8*TS*64];
__device__ __align__(128) float g_M[(size_t)36*512*TS];
__device__ float g_tmp[HWSZ];

#define XPART 33024
#define XBUF 66048
#define WOFF 132096
#define WPART 16384
#define WBUF 32768
#define SMEM_TOTAL 197632
#define X2PART 65792
#define W2OFF 131584
#define W2PART 8192
#define W2TAP 16384
#define SMEM2_TOTAL 180736
#define GXPART 32768
#define GXBUF 65536
#define GWOFF 131072
#define GWPART 16384
#define GWBUF 32768
#define GSMEM 196608

__device__ __forceinline__ uint32_t smem_u32(const void* p) {
    uint32_t a;
    asm("{ .reg .u64 t; cvta.to.shared.u64 t, %1; cvt.u32.u64 %0, t; }" : "=r"(a) : "l"(p));
    return a;
}
__device__ __forceinline__ void cp16(uint32_t dst, const void* src, uint32_t n) {
    asm volatile("cp.async.cg.shared.global [%0], [%1], 16, %2;"
                 :: "r"(dst), "l"(src), "r"(n) : "memory");
}
__device__ __forceinline__ void ldsm4(uint32_t (&r)[4], uint32_t a) {
    asm volatile("ldmatrix.sync.aligned.m8n8.x4.shared.b16 {%0,%1,%2,%3}, [%4];"
                 : "=r"(r[0]), "=r"(r[1]), "=r"(r[2]), "=r"(r[3]) : "r"(a));
}
__device__ __forceinline__ void mma16816(float* c, const uint32_t* a, const uint32_t* b) {
    asm volatile(
        "mma.sync.aligned.m16n8k16.row.col.f32.bf16.bf16.f32 "
        "{%0,%1,%2,%3}, {%4,%5,%6,%7}, {%8,%9}, {%0,%1,%2,%3};"
        : "+f"(c[0]), "+f"(c[1]), "+f"(c[2]), "+f"(c[3])
        : "r"(a[0]), "r"(a[1]), "r"(a[2]), "r"(a[3]), "r"(b[0]), "r"(b[1]));
}
__device__ __forceinline__ void split_store(__nv_bfloat16* hi_p, __nv_bfloat16* lo_p, float v) {
    __nv_bfloat16 h = __float2bfloat16(v);
    *hi_p = h;
    *lo_p = __float2bfloat16(v - __bfloat162float(h));
}

// ---------------- direct-path weight transform (9 taps) ----------------
__global__ void wtrans_kernel(const float* __restrict__ w, int cout, int coutPad,
                              int cin, int nck) {
    int e = blockIdx.x * blockDim.x + threadIdx.x;
    if (e >= 2 * nck * 9 * coutPad * 64) return;
    int sc  = e & 63;
    int co  = (e >> 6) % coutPad;
    int blk = e / (64 * coutPad);
    int tap = blk % 9, ck2 = blk / 9;
    int part = (ck2 >= nck) ? 1 : 0;
    int ck = part ? ck2 - nck : ck2;
    int c = sc ^ ((co & 7) << 3);
    float v = 0.f;
    if (co < cout) v = w[((size_t)co * cin + ck * 64 + c) * 9 + tap];
    __nv_bfloat16 h = __float2bfloat16(v);
    g_w2[e] = part ? __float2bfloat16(v - __bfloat162float(h)) : h;
}

// ---------------- winograd F(4,3) weight transform (fast) ----------------
__global__ void wg_wtrans_kernel(const float* __restrict__ w, int cout, int coutPad,
                                 int cin, int nck) {
    int e = blockIdx.x * blockDim.x + threadIdx.x;
    if (e >= nck * coutPad * 32) return;
    int c2 = e & 31;
    int co = (e >> 5) % coutPad;
    int ck = e / (32 * coutPad);
    int s = (co & 7) << 3;
    int sc0 = 2 * c2;
    int ca = sc0 ^ s;
    float U[2][36];
#pragma unroll
    for (int ch = 0; ch < 2; ch++) {
        float g[9];
#pragma unroll
        for (int i = 0; i < 9; i++) g[i] = 0.f;
        if (co < cout) {
            const float* gw = &w[((size_t)co * cin + ck * 64 + ca + ch) * 9];
#pragma unroll
            for (int i = 0; i < 9; i++) g[i] = gw[i];
        }
        float T1[6][3];
#pragma unroll
        for (int b = 0; b < 3; b++) {
            float a0 = g[b], a1 = g[3 + b], a2 = g[6 + b];
            T1[0][b] = 0.25f * a0;
            T1[1][b] = (-1.f / 6.f) * (a0 + a1 + a2);
            T1[2][b] = (1.f / 6.f) * (-a0 + a1 - a2);
            T1[3][b] = (1.f / 24.f) * a0 + (1.f / 12.f) * a1 + (1.f / 6.f) * a2;
            T1[4][b] = (1.f / 24.f) * a0 - (1.f / 12.f) * a1 + (1.f / 6.f) * a2;
            T1[5][b] = a2;
        }
#pragma unroll
        for (int i = 0; i < 6; i++) {
            float t0 = T1[i][0], t1 = T1[i][1], t2 = T1[i][2];
            U[ch][i * 6 + 0] = 0.25f * t0;
            U[ch][i * 6 + 1] = (-1.f / 6.f) * (t0 + t1 + t2);
            U[ch][i * 6 + 2] = (1.f / 6.f) * (-t0 + t1 - t2);
            U[ch][i * 6 + 3] = (1.f / 24.f) * t0 + (1.f / 12.f) * t1 + (1.f / 6.f) * t2;
            U[ch][i * 6 + 4] = (1.f / 24.f) * t0 - (1.f / 12.f) * t1 + (1.f / 6.f) * t2;
            U[ch][i * 6 + 5] = t2;
        }
    }
#pragma unroll
    for (int t = 0; t < 36; t++) {
        __nv_bfloat16 h0 = __float2bfloat16(U[0][t]);
        __nv_bfloat16 h1 = __float2bfloat16(U[1][t]);
        __nv_bfloat16 l0 = __float2bfloat16(U[0][t] - __bfloat162float(h0));
        __nv_bfloat16 l1 = __float2bfloat16(U[1][t] - __bfloat162float(h1));
        size_t offHi = ((size_t)(ck * 36 + t) * coutPad + co) * 64 + sc0;
        size_t offLo = ((size_t)((nck + ck) * 36 + t) * coutPad + co) * 64 + sc0;
        *(__nv_bfloat162*)&g_w2[offHi] = __nv_bfloat162(h0, h1);
        *(__nv_bfloat162*)&g_w2[offLo] = __nv_bfloat162(l0, l1);
    }
}

// ---------------- winograd F(4,3) input transform (one strip) ----------------
__global__ __launch_bounds__(256, 2) void wg_xtrans_kernel(
    const __nv_bfloat16* __restrict__ actIn, int nckIn, int tyBase) {
    extern __shared__ __align__(16) float xs[];  // [18][18][64]
    int tid = threadIdx.x;
    int ck = blockIdx.z;
    int tx0 = blockIdx.x * 4;
    int lty0 = blockIdx.y * 4;
    int ty0 = tyBase + lty0;
    int px0 = tx0 * 4 - 1, py0 = ty0 * 4 - 1;
    const __nv_bfloat16* hiB = actIn + (size_t)ck * CHSZ;
    const __nv_bfloat16* loB = actIn + (size_t)(nckIn + ck) * CHSZ;

    for (int i = tid; i < 18 * 18 * 32; i += 256) {
        int c2 = i & 31, rem = i >> 5;
        int cc = rem % 18, r = rem / 18;
        int gy = py0 + r, gx = px0 + cc;
        float2 v = make_float2(0.f, 0.f);
        if ((unsigned)gy < HH && (unsigned)gx < WW) {
            size_t idx = ((size_t)(gy * WW + gx)) * 64 + c2 * 2;
            float2 h = __bfloat1622float2(*(const __nv_bfloat162*)&hiB[idx]);
            float2 l = __bfloat1622float2(*(const __nv_bfloat162*)&loB[idx]);
            v = make_float2(h.x + l.x, h.y + l.y);
        }
        *(float2*)&xs[(r * 18 + cc) * 64 + c2 * 2] = v;
    }
    __syncthreads();

    for (int i8 = tid; i8 < 512; i8 += 256) {
        int c2 = i8 & 31, tl = i8 >> 5;
        int tiy = tl >> 2, tix = tl & 3;
        int c = c2 * 2;
        float Va[36], Vb[36];
#pragma unroll
        for (int ch = 0; ch < 2; ch++) {
            float t[6][6];
#pragma unroll
            for (int j = 0; j < 6; j++) {
                float d0 = xs[((4 * tiy + 0) * 18 + 4 * tix + j) * 64 + c + ch];
                float d1 = xs[((4 * tiy + 1) * 18 + 4 * tix + j) * 64 + c + ch];
                float d2 = xs[((4 * tiy + 2) * 18 + 4 * tix + j) * 64 + c + ch];
                float d3 = xs[((4 * tiy + 3) * 18 + 4 * tix + j) * 64 + c + ch];
                float d4 = xs[((4 * tiy + 4) * 18 + 4 * tix + j) * 64 + c + ch];
                float d5 = xs[((4 * tiy + 5) * 18 + 4 * tix + j) * 64 + c + ch];
                t[0][j] = 4.f * d0 - 5.f * d2 + d4;
                t[1][j] = -4.f * d1 - 4.f * d2 + d3 + d4;
                t[2][j] = 4.f * d1 - 4.f * d2 - d3 + d4;
                t[3][j] = -2.f * d1 - d2 + 2.f * d3 + d4;
                t[4][j] = 2.f * d1 - d2 - 2.f * d3 + d4;
                t[5][j] = 4.f * d1 - 5.f * d3 + d5;
            }
            float* V = ch ? Vb : Va;
#pragma unroll
            for (int i2 = 0; i2 < 6; i2++) {
                V[i2 * 6 + 0] = 4.f * t[i2][0] - 5.f * t[i2][2] + t[i2][4];
                V[i2 * 6 + 1] = -4.f * t[i2][1] - 4.f * t[i2][2] + t[i2][3] + t[i2][4];
                V[i2 * 6 + 2] = 4.f * t[i2][1] - 4.f * t[i2][2] - t[i2][3] + t[i2][4];
                V[i2 * 6 + 3] = -2.f * t[i2][1] - t[i2][2] + 2.f * t[i2][3] + t[i2][4];
                V[i2 * 6 + 4] = 2.f * t[i2][1] - t[i2][2] - 2.f * t[i2][3] + t[i2][4];
                V[i2 * 6 + 5] = 4.f * t[i2][1] - 5.f * t[i2][3] + t[i2][5];
            }
        }
        size_t ltile = (size_t)(lty0 + tiy) * 128 + tx0 + tix;
#pragma unroll
        for (int t2 = 0; t2 < 36; t2++) {
            __nv_bfloat16 ha = __float2bfloat16(Va[t2]);
            __nv_bfloat16 hb = __float2bfloat16(Vb[t2]);
            __nv_bfloat16 la = __float2bfloat16(Va[t2] - __bfloat162float(ha));
            __nv_bfloat16 lb = __float2bfloat16(Vb[t2] - __bfloat162float(hb));
            size_t off = ((size_t)(t2 * nckIn + ck) * TS + ltile) * 64 + c;
            *(__nv_bfloat162*)&g_Vhi[off] = __nv_bfloat162(ha, hb);
            *(__nv_bfloat162*)&g_Vlo[off] = __nv_bfloat162(la, lb);
        }
    }
}

// ---------------- winograd GEMM (3-term split bf16, one strip) ----------------
__global__ __launch_bounds__(256, 1) void wg_gemm_kernel(int nck, int coutTot) {
    extern __shared__ __align__(128) char sm[];
    const int tid = threadIdx.x;
    const int lane = tid & 31, wid = tid >> 5;
    const int cg = wid >> 2, pg = wid & 3;
    const int cout0 = blockIdx.x * 128;
    const int coutPad = gridDim.x * 128;
    const int tile0 = blockIdx.y * 256;
    const int comp = blockIdx.z;
    const uint32_t sb = smem_u32(sm);

    float acc[4][8][4];
#pragma unroll
    for (int a = 0; a < 4; a++)
#pragma unroll
        for (int b2 = 0; b2 < 8; b2++)
#pragma unroll
            for (int c = 0; c < 4; c++) acc[a][b2][c] = 0.f;

    const int l7 = lane & 7;
    const int arow_base = cg * 64 + ((lane >> 3) & 1) * 8 + l7;
    const int akg_add = lane >> 4;
    const int bpx_base = pg * 64 + ((lane >> 4) & 1) * 8 + l7;
    const int bkg_add = (lane >> 3) & 1;

    auto stage_it = [&](int ck) {
        uint32_t wdst = sb + GWOFF + (ck & 1) * GWBUF;
        for (int i = tid; i < 2048; i += 256) {
            int part = i >> 10, r3 = i & 1023;
            const char* src = (const char*)g_w2 +
                ((size_t)((part * nck + ck) * 36 + comp) * coutPad + cout0) * 128 + r3 * 16;
            cp16(wdst + part * GWPART + r3 * 16, src, 16u);
        }
        uint32_t xdst = sb + (ck & 1) * GXBUF;
        for (int i = tid; i < 4096; i += 256) {
            int part = i >> 11, rem = i & 2047;
            int xi = rem >> 3, gs = rem & 7;
            const char* src = (const char*)(part ? g_Vlo : g_Vhi) +
                ((size_t)(comp * nck + ck) * TS + tile0 + xi) * 128 + gs * 16;
            cp16(xdst + part * GXPART + xi * 128 + ((gs ^ (xi & 7)) << 4), src, 16u);
        }
        asm volatile("cp.async.commit_group;" ::: "memory");
    };

    stage_it(0);
    for (int it = 0; it < nck; it++) {
        asm volatile("cp.async.wait_group 0;" ::: "memory");
        __syncthreads();
        if (it + 1 < nck) stage_it(it + 1);

        uint32_t wcur = sb + GWOFF + (it & 1) * GWBUF;
        uint32_t xcur = sb + (it & 1) * GXBUF;
#pragma unroll
        for (int kk = 0; kk < 4; kk++) {
            uint32_t Ah[4][4], Al[4][4], Bf[4][4];
            uint32_t akg = ((uint32_t)(kk * 2 + akg_add) ^ (uint32_t)l7) << 4;
#pragma unroll
            for (int mf = 0; mf < 4; mf++)
                ldsm4(Ah[mf], wcur + (arow_base + mf * 16) * 128 + akg);
#pragma unroll
            for (int q = 0; q < 4; q++) {
                int xi = bpx_base + q * 16;
                ldsm4(Bf[q], xcur + xi * 128 + (((uint32_t)(kk * 2 + bkg_add) ^ (uint32_t)(xi & 7)) << 4));
            }
#pragma unroll
            for (int mf = 0; mf < 4; mf++)
#pragma unroll
                for (int q = 0; q < 4; q++) {
                    mma16816(acc[mf][2 * q], Ah[mf], &Bf[q][0]);
                    mma16816(acc[mf][2 * q + 1], Ah[mf], &Bf[q][2]);
                }
#pragma unroll
            for (int mf = 0; mf < 4; mf++)
                ldsm4(Al[mf], wcur + GWPART + (arow_base + mf * 16) * 128 + akg);
#pragma unroll
            for (int mf = 0; mf < 4; mf++)
#pragma unroll
                for (int q = 0; q < 4; q++) {
                    mma16816(acc[mf][2 * q], Al[mf], &Bf[q][0]);
                    mma16816(acc[mf][2 * q + 1], Al[mf], &Bf[q][2]);
                }
#pragma unroll
            for (int q = 0; q < 4; q++) {
                int xi = bpx_base + q * 16;
                ldsm4(Bf[q], xcur + GXPART + xi * 128 + (((uint32_t)(kk * 2 + bkg_add) ^ (uint32_t)(xi & 7)) << 4));
            }
#pragma unroll
            for (int mf = 0; mf < 4; mf++)
#pragma unroll
                for (int q = 0; q < 4; q++) {
                    mma16816(acc[mf][2 * q], Ah[mf], &Bf[q][0]);
                    mma16816(acc[mf][2 * q + 1], Ah[mf], &Bf[q][2]);
                }
        }
    }

    float* Mp = g_M + (size_t)comp * coutTot * TS;
#pragma unroll
    for (int mf = 0; mf < 4; mf++) {
        int co = cout0 + cg * 64 + mf * 16 + (lane >> 2);
#pragma unroll
        for (int nf = 0; nf < 8; nf++) {
            int tile = tile0 + pg * 64 + nf * 8 + ((lane & 3) << 1);
            *(float2*)&Mp[(size_t)co * TS + tile] = make_float2(acc[mf][nf][0], acc[mf][nf][1]);
            *(float2*)&Mp[(size_t)(co + 8) * TS + tile] = make_float2(acc[mf][nf][2], acc[mf][nf][3]);
        }
    }
}

// ---------------- winograd F(4,3) output transform (one strip) ----------------
__global__ __launch_bounds__(256, 1) void wg_ytrans_kernel(
    __nv_bfloat16* __restrict__ actOut, const float* __restrict__ bias,
    const float* __restrict__ prelu, int coutTot, int nckOut, int tyBase) {
    extern __shared__ __align__(16) char ysm[];
    __nv_bfloat16* ysHi = (__nv_bfloat16*)ysm;
    __nv_bfloat16* ysLo = (__nv_bfloat16*)(ysm + 65536);
    int tid = threadIdx.x;
    int tx0t = blockIdx.x * 32;
    int lty = blockIdx.y;
    int co0 = blockIdx.z * 64;
    float alpha = prelu[0];

    for (int i = tid; i < 2048; i += 256) {
        int tl = i & 31, cl = i >> 5;
        int co = co0 + cl;
        size_t ltile = (size_t)lty * 128 + tx0t + tl;
        float q[4][6];
#pragma unroll
        for (int l = 0; l < 6; l++) {
            float m0 = g_M[((size_t)(0 * 6 + l) * coutTot + co) * TS + ltile];
            float m1 = g_M[((size_t)(1 * 6 + l) * coutTot + co) * TS + ltile];
            float m2 = g_M[((size_t)(2 * 6 + l) * coutTot + co) * TS + ltile];
            float m3 = g_M[((size_t)(3 * 6 + l) * coutTot + co) * TS + ltile];
            float m4 = g_M[((size_t)(4 * 6 + l) * coutTot + co) * TS + ltile];
            float m5 = g_M[((size_t)(5 * 6 + l) * coutTot + co) * TS + ltile];
            q[0][l] = m0 + m1 + m2 + m3 + m4;
            q[1][l] = m1 - m2 + 2.f * (m3 - m4);
            q[2][l] = m1 + m2 + 4.f * (m3 + m4);
            q[3][l] = m1 - m2 + 8.f * (m3 - m4) + m5;
        }
        float bv = bias[co];
#pragma unroll
        for (int r = 0; r < 4; r++) {
            float y0 = q[r][0] + q[r][1] + q[r][2] + q[r][3] + q[r][4] + bv;
            float y1 = q[r][1] - q[r][2] + 2.f * (q[r][3] - q[r][4]) + bv;
            float y2 = q[r][1] + q[r][2] + 4.f * (q[r][3] + q[r][4]) + bv;
            float y3 = q[r][1] - q[r][2] + 8.f * (q[r][3] - q[r][4]) + q[r][5] + bv;
            float ys[4] = {y0, y1, y2, y3};
#pragma unroll
            for (int s = 0; s < 4; s++) {
                float v = ys[s];
                v = v >= 0.f ? v : alpha * v;
                int px = tl * 4 + s;
                int pc = cl ^ ((px & 7) << 3);
                __nv_bfloat16 h = __float2bfloat16(v);
                ysHi[(r * 128 + px) * 64 + pc] = h;
                ysLo[(r * 128 + px) * 64 + pc] = __float2bfloat16(v - __bfloat162float(h));
            }
        }
    }
    __syncthreads();

    int chunk = co0 >> 6;
    for (int i = tid; i < 4096; i += 256) {
        int r = i >> 10, rem = i & 1023;
        int px = rem >> 3, g = rem & 7;
        int pg2 = g ^ (px & 7);
        int gy = (tyBase + lty) * 4 + r, gx = tx0t * 4 + px;
        size_t off = (size_t)chunk * CHSZ + ((size_t)(gy * WW + gx)) * 64 + g * 8;
        *(uint4*)&actOut[off] = *(uint4*)&ysHi[(r * 128 + px) * 64 + pg2 * 8];
        *(uint4*)&actOut[(size_t)nckOut * CHSZ + off] = *(uint4*)&ysLo[(r * 128 + px) * 64 + pg2 * 8];
    }
}

// ---------------- layer 0 ----------------
__global__ void layer0_kernel(const float* __restrict__ A, const float* __restrict__ w,
                              const float* __restrict__ b, const float* __restrict__ p) {
    int idx = blockIdx.x * blockDim.x + threadIdx.x;
    if (idx >= HWSZ) return;
    float a = A[idx], alpha = p[0];
    size_t base = (size_t)idx * 64;
#pragma unroll
    for (int c = 0; c < 64; c++) {
        float v = fmaf(w[c], a, b[c]);
        v = v >= 0.f ? v : alpha * v;
        split_store(&g_actA[base + c], &g_actA[CHSZ + base + c], v);
    }
}

// ---------------- direct conv (L1): 128 couts x 256 px ----------------
__global__ __launch_bounds__(256, 1) void conv_mma_kernel(
    const __nv_bfloat16* __restrict__ actIn, __nv_bfloat16* __restrict__ actOut,
    const float* __restrict__ bias, const float* __restrict__ prelu,
    int nck, int nckOut, int coutReal) {
    extern __shared__ __align__(128) char sm[];
    const int tid = threadIdx.x;
    const int lane = tid & 31, wid = tid >> 5;
    const int cg = wid >> 2, pg = wid & 3;
    const int cout0 = blockIdx.x * 128;
    const int coutPad = gridDim.x * 128;
    const int x0 = blockIdx.y * 256;
    const int y0 = blockIdx.z;
    const uint32_t sb = smem_u32(sm);

    float acc[4][8][4];
#pragma unroll
    for (int a = 0; a < 4; a++)
#pragma unroll
        for (int b2 = 0; b2 < 8; b2++)
#pragma unroll
            for (int c = 0; c < 4; c++) acc[a][b2][c] = 0.f;

    const int l7 = lane & 7;
    const int arow_base = cg * 64 + ((lane >> 3) & 1) * 8 + l7;
    const int akg_add = lane >> 4;
    const int bpx_base = pg * 64 + ((lane >> 4) & 1) * 8 + l7;
    const int bkg_add = (lane >> 3) & 1;
    const int niter = nck * 9;

    auto stage_it = [&](int jt) {
        int ck = jt / 9, r = jt - ck * 9, dy = r / 3, dx = r - dy * 3;
        uint32_t wdst = sb + WOFF + (jt & 1) * WBUF;
        for (int i = tid; i < 2048; i += 256) {
            int part = i >> 10;
            int r3 = i & 1023;
            const char* src = (const char*)g_w2 +
                ((((size_t)(part * nck + ck) * 9 + dy * 3 + dx)) * coutPad + cout0) * 128 +
                r3 * 16;
            cp16(wdst + part * WPART + r3 * 16, src, 16u);
        }
        if (dx == 0) {
            int y = y0 + dy - 1;
            bool yok = (unsigned)y < HH;
            uint32_t xdst = sb + ((jt / 3) & 1) * XBUF;
            for (int i = tid; i < 4128; i += 256) {
                int part = i / 2064;
                int rem = i - part * 2064;
                int xi = rem >> 3, gs = rem & 7;
                int gx = x0 - 1 + xi;
                bool ok = yok && (unsigned)gx < WW;
                const char* src = (const char*)(actIn + (size_t)(part * nck + ck) * CHSZ) +
                                  (size_t)(ok ? (y * WW + gx) : 0) * 128 + gs * 16;
                cp16(xdst + part * XPART + xi * 128 + ((gs ^ (xi & 7)) << 4), src, ok ? 16u : 0u);
            }
        }
        asm volatile("cp.async.commit_group;" ::: "memory");
    };

    stage_it(0);
    for (int it = 0; it < niter; it++) {
        asm volatile("cp.async.wait_group 0;" ::: "memory");
        __syncthreads();
        if (it + 1 < niter) stage_it(it + 1);

        int dx = it % 3;
        uint32_t wcur = sb + WOFF + (it & 1) * WBUF;
        uint32_t xcur = sb + ((it / 3) & 1) * XBUF;
#pragma unroll
        for (int kk = 0; kk < 4; kk++) {
            uint32_t Ah[4][4], Al[4][4], Bf[4][4];
            uint32_t akg = ((uint32_t)(kk * 2 + akg_add) ^ (uint32_t)l7) << 4;
#pragma unroll
            for (int mf = 0; mf < 4; mf++)
                ldsm4(Ah[mf], wcur + (arow_base + mf * 16) * 128 + akg);
#pragma unroll
            for (int q = 0; q < 4; q++) {
                int xi = bpx_base + q * 16 + dx;
                ldsm4(Bf[q], xcur + xi * 128 + (((uint32_t)(kk * 2 + bkg_add) ^ (uint32_t)(xi & 7)) << 4));
            }
#pragma unroll
            for (int mf = 0; mf < 4; mf++)
#pragma unroll
                for (int q = 0; q < 4; q++) {
                    mma16816(acc[mf][2 * q], Ah[mf], &Bf[q][0]);
                    mma16816(acc[mf][2 * q + 1], Ah[mf], &Bf[q][2]);
                }
#pragma unroll
            for (int mf = 0; mf < 4; mf++)
                ldsm4(Al[mf], wcur + WPART + (arow_base + mf * 16) * 128 + akg);
#pragma unroll
            for (int mf = 0; mf < 4; mf++)
#pragma unroll
                for (int q = 0; q < 4; q++) {
                    mma16816(acc[mf][2 * q], Al[mf], &Bf[q][0]);
                    mma16816(acc[mf][2 * q + 1], Al[mf], &Bf[q][2]);
                }
#pragma unroll
            for (int q = 0; q < 4; q++) {
                int xi = bpx_base + q * 16 + dx;
                ldsm4(Bf[q], xcur + XPART + xi * 128 + (((uint32_t)(kk * 2 + bkg_add) ^ (uint32_t)(xi & 7)) << 4));
            }
#pragma unroll
            for (int mf = 0; mf < 4; mf++)
#pragma unroll
                for (int q = 0; q < 4; q++) {
                    mma16816(acc[mf][2 * q], Ah[mf], &Bf[q][0]);
                    mma16816(acc[mf][2 * q + 1], Ah[mf], &Bf[q][2]);
                }
        }
    }
    __syncthreads();

    float* esm = (float*)sm;
    float alpha = prelu[0];
#pragma unroll
    for (int mf = 0; mf < 4; mf++) {
        int cl = cg * 64 + mf * 16 + (lane >> 2);
        float bl = (cout0 + cl < coutReal) ? bias[cout0 + cl] : 0.f;
        float bh = (cout0 + cl + 8 < coutReal) ? bias[cout0 + cl + 8] : 0.f;
#pragma unroll
        for (int nf = 0; nf < 8; nf++) {
            int p = pg * 64 + nf * 8 + ((lane & 3) << 1);
#pragma unroll
            for (int e = 0; e < 4; e++) {
                int c = cl + ((e & 2) ? 8 : 0);
                float v = acc[mf][nf][e] + ((e & 2) ? bh : bl);
                v = v >= 0.f ? v : alpha * v;
                esm[(p + (e & 1)) * 128 + c] = v;
            }
        }
    }
    __syncthreads();

    size_t rowbase = (size_t)y0 * WW + x0;
#pragma unroll
    for (int g = 0; g < 16; g++) {
        int idx = g * 256 + tid;
        int px = idx >> 4;
        int rem = idx & 15;
        int chunk = rem >> 3, grp = rem & 7;
        int cb = chunk * 64 + grp * 8;
        if (cout0 + cb >= coutReal) continue;
        const float* s = &esm[px * 128 + cb];
        __nv_bfloat16 hi[8], lo[8];
#pragma unroll
        for (int j = 0; j < 8; j++) {
            float v = s[j];
            __nv_bfloat16 h = __float2bfloat16(v);
            hi[j] = h;
            lo[j] = __float2bfloat16(v - __bfloat162float(h));
        }
        size_t off = (size_t)((cout0 + cb) >> 6) * CHSZ + (rowbase + px) * 64 + (cb & 63);
        *(uint4*)&actOut[off] = *(uint4*)hi;
        *(uint4*)&actOut[(size_t)nckOut * CHSZ + off] = *(uint4*)lo;
    }
}

// ---------------- direct conv (L4): 64 couts x 512 px ----------------
__global__ __launch_bounds__(256, 1) void conv_mma64_kernel(
    const __nv_bfloat16* __restrict__ actIn, __nv_bfloat16* __restrict__ actOut,
    const float* __restrict__ bias, const float* __restrict__ prelu,
    int nck, int nckOut, int coutReal) {
    extern __shared__ __align__(128) char sm[];
    const int tid = threadIdx.x;
    const int lane = tid & 31, wid = tid >> 5;
    const int pg = wid;
    const int y0 = blockIdx.z;
    const uint32_t sb = smem_u32(sm);

    float acc[4][8][4];
#pragma unroll
    for (int a = 0; a < 4; a++)
#pragma unroll
        for (int b2 = 0; b2 < 8; b2++)
#pragma unroll
            for (int c = 0; c < 4; c++) acc[a][b2][c] = 0.f;

    const int l7 = lane & 7;
    const int arow_base = ((lane >> 3) & 1) * 8 + l7;
    const int akg_add = lane >> 4;
    const int bpx_base = pg * 64 + ((lane >> 4) & 1) * 8 + l7;
    const int bkg_add = (lane >> 3) & 1;

    for (int it2 = 0; it2 < nck * 3; it2++) {
        int ck = it2 / 3, dy = it2 - ck * 3;
        if (it2) __syncthreads();
        int y = y0 + dy - 1;
        bool yok = (unsigned)y < HH;
        for (int i = tid; i < 8224; i += 256) {
            int part = i / 4112;
            int rem = i - part * 4112;
            int xi = rem >> 3, gs = rem & 7;
            int gx = xi - 1;
            bool ok = yok && (unsigned)gx < WW;
            const char* src = (const char*)(actIn + (size_t)(part * nck + ck) * CHSZ) +
                              (size_t)(ok ? (y * WW + gx) : 0) * 128 + gs * 16;
            cp16(sb + part * X2PART + xi * 128 + ((gs ^ (xi & 7)) << 4), src, ok ? 16u : 0u);
        }
        for (int i = tid; i < 3072; i += 256) {
            int dx = i / 1024;
            int rem = i & 1023;
            int part = rem >> 9;
            int r3 = rem & 511;
            const char* src = (const char*)g_w2 +
                ((((size_t)(part * nck + ck) * 9 + dy * 3 + dx)) * 64) * 128 + r3 * 16;
            cp16(sb + W2OFF + dx * W2TAP + part * W2PART + r3 * 16, src, 16u);
        }
        asm volatile("cp.async.wait_all;" ::: "memory");
        __syncthreads();

#pragma unroll
        for (int dx = 0; dx < 3; dx++) {
            uint32_t wcur = sb + W2OFF + dx * W2TAP;
#pragma unroll
            for (int kk = 0; kk < 4; kk++) {
                uint32_t Ah[4][4], Al[4][4], Bf[4][4];
                uint32_t akg = ((uint32_t)(kk * 2 + akg_add) ^ (uint32_t)l7) << 4;
#pragma unroll
                for (int mf = 0; mf < 4; mf++)
                    ldsm4(Ah[mf], wcur + (arow_base + mf * 16) * 128 + akg);
#pragma unroll
                for (int q = 0; q < 4; q++) {
                    int xi = bpx_base + q * 16 + dx;
                    ldsm4(Bf[q], sb + xi * 128 + (((uint32_t)(kk * 2 + bkg_add) ^ (uint32_t)(xi & 7)) << 4));
                }
#pragma unroll
                for (int mf = 0; mf < 4; mf++)
#pragma unroll
                    for (int q = 0; q < 4; q++) {
                        mma16816(acc[mf][2 * q], Ah[mf], &Bf[q][0]);
                        mma16816(acc[mf][2 * q + 1], Ah[mf], &Bf[q][2]);
                    }
#pragma unroll
                for (int mf = 0; mf < 4; mf++)
                    ldsm4(Al[mf], wcur + W2PART + (arow_base + mf * 16) * 128 + akg);
#pragma unroll
                for (int mf = 0; mf < 4; mf++)
#pragma unroll
                    for (int q = 0; q < 4; q++) {
                        mma16816(acc[mf][2 * q], Al[mf], &Bf[q][0]);
                        mma16816(acc[mf][2 * q + 1], Al[mf], &Bf[q][2]);
                    }
#pragma unroll
                for (int q = 0; q < 4; q++) {
                    int xi = bpx_base + q * 16 + dx;
                    ldsm4(Bf[q], sb + X2PART + xi * 128 + (((uint32_t)(kk * 2 + bkg_add) ^ (uint32_t)(xi & 7)) << 4));
                }
#pragma unroll
                for (int mf = 0; mf < 4; mf++)
#pragma unroll
                    for (int q = 0; q < 4; q++) {
                        mma16816(acc[mf][2 * q], Ah[mf], &Bf[q][0]);
                        mma16816(acc[mf][2 * q + 1], Ah[mf], &Bf[q][2]);
                    }
            }
        }
    }
    __syncthreads();

    float* esm = (float*)sm;
    float alpha = prelu[0];
#pragma unroll
    for (int mf = 0; mf < 4; mf++) {
        int cl = mf * 16 + (lane >> 2);
        float bl = bias[cl];
        float bh = bias[cl + 8];
#pragma unroll
        for (int nf = 0; nf < 8; nf++) {
            int p = pg * 64 + nf * 8 + ((lane & 3) << 1);
#pragma unroll
            for (int e = 0; e < 4; e++) {
                int c = cl + ((e & 2) ? 8 : 0);
                float v = acc[mf][nf][e] + ((e & 2) ? bh : bl);
                v = v >= 0.f ? v : alpha * v;
                esm[(p + (e & 1)) * 64 + c] = v;
            }
        }
    }
    __syncthreads();

    size_t rowbase = (size_t)y0 * WW;
#pragma unroll
    for (int g = 0; g < 16; g++) {
        int idx = g * 256 + tid;
        int px = idx >> 3;
        int cb = (idx & 7) * 8;
        const float* s = &esm[px * 64 + cb];
        __nv_bfloat16 hi[8], lo[8];
#pragma unroll
        for (int j = 0; j < 8; j++) {
            float v = s[j];
            __nv_bfloat16 h = __float2bfloat16(v);
            hi[j] = h;
            lo[j] = __float2bfloat16(v - __bfloat162float(h));
        }
        size_t off = (rowbase + px) * 64 + cb;
        *(uint4*)&actOut[off] = *(uint4*)hi;
        *(uint4*)&actOut[(size_t)nckOut * CHSZ + off] = *(uint4*)lo;
    }
}

// ---------------- L5 + symmetrize ----------------
__global__ void conv_last_kernel(const __nv_bfloat16* __restrict__ act,
                                 const float* __restrict__ w, const float* __restrict__ b,
                                 const float* __restrict__ p, float* __restrict__ out) {
    int x = blockIdx.x * 32 + (threadIdx.x & 31);
    int y = blockIdx.y * 8 + (threadIdx.x >> 5);
    float acc = 0.f;
#pragma unroll
    for (int dy = 0; dy < 3; dy++) {
        int gy = y + dy - 1;
        if ((unsigned)gy >= HH) continue;
#pragma unroll
        for (int dx = 0; dx < 3; dx++) {
            int gx = x + dx - 1;
            if ((unsigned)gx >= WW) continue;
            size_t base = (size_t)(gy * WW + gx) * 64;
            const __nv_bfloat162* hi2 = (const __nv_bfloat162*)&act[base];
            const __nv_bfloat162* lo2 = (const __nv_bfloat162*)&act[CHSZ + base];
#pragma unroll
            for (int c2 = 0; c2 < 32; c2++) {
                float2 h = __bfloat1622float2(hi2[c2]);
                float2 l = __bfloat1622float2(lo2[c2]);
                acc = fmaf(h.x + l.x, w[(c2 * 2) * 9 + dy * 3 + dx], acc);
                acc = fmaf(h.y + l.y, w[(c2 * 2 + 1) * 9 + dy * 3 + dx], acc);
            }
        }
    }
    float v = acc + b[0];
    v = v >= 0.f ? v : p[0] * v;
    out[y * WW + x] = v;
}

__global__ void sym_kernel(const float* __restrict__ t, float* __restrict__ out) {
    int x = blockIdx.x * 32 + (threadIdx.x & 31);
    int y = blockIdx.y * 8 + (threadIdx.x >> 5);
    out[y * WW + x] = 0.5f * (t[y * WW + x] + t[x * WW + y]);
}

// ---------------------------------------------------------------------------
extern "C" void kernel_launch(void* const* d_in, const int* in_sizes, int n_in,
                              void* d_out, int out_size) {
    const float* A = (const float*)d_in[0];
    const float* wp[6]; const float* bp[6]; const float* pp[6];
    for (int i = 0; i < 6; i++) {
        wp[i] = (const float*)d_in[1 + 3 * i];
        bp[i] = (const float*)d_in[2 + 3 * i];
        pp[i] = (const float*)d_in[3 + 3 * i];
    }
    __nv_bfloat16 *actA, *actB; float* tmp;
    cudaGetSymbolAddress((void**)&actA, g_actA);
    cudaGetSymbolAddress((void**)&actB, g_actB);
    cudaGetSymbolAddress((void**)&tmp, g_tmp);

    cudaFuncSetAttribute(conv_mma_kernel, cudaFuncAttributeMaxDynamicSharedMemorySize, SMEM_TOTAL);
    cudaFuncSetAttribute(conv_mma64_kernel, cudaFuncAttributeMaxDynamicSharedMemorySize, SMEM2_TOTAL);
    cudaFuncSetAttribute(wg_gemm_kernel, cudaFuncAttributeMaxDynamicSharedMemorySize, GSMEM);
    cudaFuncSetAttribute(wg_xtrans_kernel, cudaFuncAttributeMaxDynamicSharedMemorySize, 82944);
    cudaFuncSetAttribute(wg_ytrans_kernel, cudaFuncAttributeMaxDynamicSharedMemorySize, 131072);

    layer0_kernel<<<HWSZ / 256, 256>>>(A, wp[0], bp[0], pp[0]);

    // L1 direct: 64 -> 256
    wtrans_kernel<<<(2 * 1 * 9 * 256 * 64 + 255) / 256, 256>>>(wp[1], 256, 256, 64, 1);
    conv_mma_kernel<<<dim3(2, WW / 256, HH), 256, SMEM_TOTAL>>>(actA, actB, bp[1], pp[1], 1, 4, 256);

    // L2 winograd F(4,3): 256 -> 512 (L2-resident strips)
    wg_wtrans_kernel<<<(4 * 512 * 32 + 255) / 256, 256>>>(wp[2], 512, 512, 256, 4);
    for (int s = 0; s < NSTRIP; s++) {
        int tyBase = s * 16;
        wg_xtrans_kernel<<<dim3(32, 4, 4), 256, 82944>>>(actB, 4, tyBase);
        wg_gemm_kernel<<<dim3(4, TS / 256, 36), 256, GSMEM>>>(4, 512);
        wg_ytrans_kernel<<<dim3(4, 16, 8), 256, 131072>>>(actA, bp[2], pp[2], 512, 8, tyBase);
    }

    // L3 winograd F(4,3): 512 -> 256
    wg_wtrans_kernel<<<(8 * 256 * 32 + 255) / 256, 256>>>(wp[3], 256, 256, 512, 8);
    for (int s = 0; s < NSTRIP; s++) {
        int tyBase = s * 16;
        wg_xtrans_kernel<<<dim3(32, 4, 8), 256, 82944>>>(actA, 8, tyBase);
        wg_gemm_kernel<<<dim3(2, TS / 256, 36), 256, GSMEM>>>(8, 256);
        wg_ytrans_kernel<<<dim3(4, 16, 4), 256, 131072>>>(actB, bp[3], pp[3], 256, 4, tyBase);
    }

    // L4 direct: 256 -> 64
    wtrans_kernel<<<(2 * 4 * 9 * 64 * 64 + 255) / 256, 256>>>(wp[4], 64, 64, 256, 4);
    conv_mma64_kernel<<<dim3(1, 1, HH), 256, SMEM2_TOTAL>>>(actB, actA, bp[4], pp[4], 4, 1, 64);

    conv_last_kernel<<<dim3(WW / 32, HH / 8), 256>>>(actA, wp[5], bp[5], pp[5], tmp);
    sym_kernel<<<dim3(WW / 32, HH / 8), 256>>>(tmp, (float*)d_out);
}